// round 2
// baseline (speedup 1.0000x reference)
#include <cuda_runtime.h>

// delta_layer: out[b,t,:] = [ x, delta(x), delta(delta(x)) ]
// delta(y)[t] = 0.5*(y[c(t+1)]-y[c(t-1)]) + 0.25*(y[c(t+2)]-y[c(t-2)]), c = clamp to [0,T-1]
// Shapes fixed: B=32, T=4096, D=256, window=2.
//
// Interior rows (4 <= t <= T-5): no clamping anywhere in the chain, so
// ddelta is the 9-tap self-convolution of the delta filter:
//   dd(t) = 0.0625(x[t-4]+x[t+4]) + 0.25(x[t-3]+x[t+3]) + 0.25(x[t-2]+x[t+2])
//         - 0.25(x[t-1]+x[t+1]) - 0.625 x[t]
// Edge chunks use the generic clamped formula in a separate small kernel.

#define B_N 32
#define T_N 4096
#define D4_N 64            // 256 floats / 4
#define OD4_N 192          // 768 floats / 4
#define L_N 32             // rows per thread (interior)
#define CHUNKS (T_N / L_N) // 128 chunks per batch row

__device__ __forceinline__ float4 f4_delta(float4 m2, float4 m1, float4 p1, float4 p2) {
    float4 r;
    r.x = 0.5f * (p1.x - m1.x) + 0.25f * (p2.x - m2.x);
    r.y = 0.5f * (p1.y - m1.y) + 0.25f * (p2.y - m2.y);
    r.z = 0.5f * (p1.z - m1.z) + 0.25f * (p2.z - m2.z);
    r.w = 0.5f * (p1.w - m1.w) + 0.25f * (p2.w - m2.w);
    return r;
}

__device__ __forceinline__ float dd9(float a0, float a1, float a2, float a3, float a4,
                                     float a5, float a6, float a7, float a8) {
    // c = [1/16, 1/4, 1/4, -1/4, -5/8, -1/4, 1/4, 1/4, 1/16]
    return 0.0625f * (a0 + a8) + 0.25f * (a1 + a7) + 0.25f * (a2 + a6)
         - 0.25f * (a3 + a5) - 0.625f * a4;
}

__global__ void __launch_bounds__(128, 8)
delta_interior_kernel(const float4* __restrict__ x, float4* __restrict__ out) {
    const int d4    = threadIdx.x;                         // 0..63
    const int chunk = 1 + blockIdx.x * 2 + threadIdx.y;    // 1..126 (interior)
    const int b     = blockIdx.y;
    const int t0    = chunk * L_N;

    const float4* __restrict__ xb = x   + (size_t)b * T_N * D4_N  + d4;
    float4*       __restrict__ ob = out + (size_t)b * T_N * OD4_N + d4;

    // 9-deep ring: r0..r8 = x[t0-4 .. t0+4]  (all in-bounds for interior chunks)
    float4 r0 = __ldg(xb + (size_t)(t0 - 4) * D4_N);
    float4 r1 = __ldg(xb + (size_t)(t0 - 3) * D4_N);
    float4 r2 = __ldg(xb + (size_t)(t0 - 2) * D4_N);
    float4 r3 = __ldg(xb + (size_t)(t0 - 1) * D4_N);
    float4 r4 = __ldg(xb + (size_t)(t0    ) * D4_N);
    float4 r5 = __ldg(xb + (size_t)(t0 + 1) * D4_N);
    float4 r6 = __ldg(xb + (size_t)(t0 + 2) * D4_N);
    float4 r7 = __ldg(xb + (size_t)(t0 + 3) * D4_N);
    float4 r8 = __ldg(xb + (size_t)(t0 + 4) * D4_N);

#pragma unroll 8
    for (int i = 0; i < L_N; ++i) {
        const int t = t0 + i;
        const size_t orow = (size_t)t * OD4_N;

        __stcs(ob + orow, r4);                              // x
        __stcs(ob + orow + D4_N, f4_delta(r2, r3, r5, r6)); // delta

        float4 dd;
        dd.x = dd9(r0.x, r1.x, r2.x, r3.x, r4.x, r5.x, r6.x, r7.x, r8.x);
        dd.y = dd9(r0.y, r1.y, r2.y, r3.y, r4.y, r5.y, r6.y, r7.y, r8.y);
        dd.z = dd9(r0.z, r1.z, r2.z, r3.z, r4.z, r5.z, r6.z, r7.z, r8.z);
        dd.w = dd9(r0.w, r1.w, r2.w, r3.w, r4.w, r5.w, r6.w, r7.w, r8.w);
        __stcs(ob + orow + 2 * D4_N, dd);                   // double delta

        // shift ring, prefetch x[t+5] (max index: t0+31+5 = t0+36 <= T-28 for interior)
        r0 = r1; r1 = r2; r2 = r3; r3 = r4; r4 = r5; r5 = r6; r6 = r7; r7 = r8;
        r8 = __ldg(xb + (size_t)(t + 5) * D4_N);
    }
}

// Edge chunks (chunk 0 and chunk CHUNKS-1): generic clamped math, L1-cached reloads.
__global__ void __launch_bounds__(64)
delta_edge_kernel(const float4* __restrict__ x, float4* __restrict__ out) {
    const int d4 = threadIdx.x;                                   // 0..63
    const int b  = blockIdx.y;
    const int t0 = (blockIdx.x == 0) ? 0 : (T_N - L_N);

    const float4* __restrict__ xb = x   + (size_t)b * T_N * D4_N  + d4;
    float4*       __restrict__ ob = out + (size_t)b * T_N * OD4_N + d4;

    auto LD = [&](int t) -> float4 {
        t = t < 0 ? 0 : (t > T_N - 1 ? T_N - 1 : t);
        return __ldg(xb + (size_t)t * D4_N);
    };
    auto DELTA_AT = [&](int s) -> float4 {
        s = s < 0 ? 0 : (s > T_N - 1 ? T_N - 1 : s);
        return f4_delta(LD(s - 2), LD(s - 1), LD(s + 1), LD(s + 2));
    };

    for (int i = 0; i < L_N; ++i) {
        const int t = t0 + i;
        const size_t orow = (size_t)t * OD4_N;
        ob[orow]        = LD(t);
        ob[orow + D4_N] = DELTA_AT(t);
        ob[orow + 2 * D4_N] =
            f4_delta(DELTA_AT(t - 2), DELTA_AT(t - 1), DELTA_AT(t + 1), DELTA_AT(t + 2));
    }
}

extern "C" void kernel_launch(void* const* d_in, const int* in_sizes, int n_in,
                              void* d_out, int out_size) {
    const float4* x = (const float4*)d_in[0];
    float4* out     = (float4*)d_out;
    // d_in[1] = window (always 2) — baked in.

    // Edge kernel first (tiny), overlaps with interior.
    dim3 eblock(D4_N, 1);
    dim3 egrid(2, B_N);
    delta_edge_kernel<<<egrid, eblock>>>(x, out);

    // Interior: chunks 1..126 per batch, 2 chunks per block.
    dim3 iblock(D4_N, 2);              // 128 threads
    dim3 igrid((CHUNKS - 2) / 2, B_N); // (63, 32) = 2016 blocks
    delta_interior_kernel<<<igrid, iblock>>>(x, out);
}

// round 3
// speedup vs baseline: 1.1967x; 1.1967x over previous
#include <cuda_runtime.h>

// delta_layer: out[b,t,:] = [ x, delta(x), delta(delta(x)) ]
// delta(y)[t] = 0.5*(y[c(t+1)]-y[c(t-1)]) + 0.25*(y[c(t+2)]-y[c(t-2)]), c = clamp to [0,T-1]
// Shapes fixed: B=32, T=4096, D=256, window=2.
//
// Single kernel. Interior chunks (no clamping in the whole chain) use a 9-deep
// register ring and the fused 9-tap double-delta filter:
//   dd(t) = 0.0625(x[t-4]+x[t+4]) + 0.25(x[t-3]+x[t+3]) + 0.25(x[t-2]+x[t+2])
//         - 0.25(x[t-1]+x[t+1]) - 0.625 x[t]
// The two edge chunks per batch row (t in [0,32) and [T-32,T)) take a generic
// clamped path inside the same kernel (uniform per warp, 64/4096 chunk-slots).

#define B_N 32
#define T_N 4096
#define D4_N 64            // 256 floats / 4
#define OD4_N 192          // 768 floats / 4
#define L_N 32             // rows per thread chunk
#define CHUNKS (T_N / L_N) // 128

__device__ __forceinline__ float4 f4_delta(float4 m2, float4 m1, float4 p1, float4 p2) {
    float4 r;
    r.x = 0.5f * (p1.x - m1.x) + 0.25f * (p2.x - m2.x);
    r.y = 0.5f * (p1.y - m1.y) + 0.25f * (p2.y - m2.y);
    r.z = 0.5f * (p1.z - m1.z) + 0.25f * (p2.z - m2.z);
    r.w = 0.5f * (p1.w - m1.w) + 0.25f * (p2.w - m2.w);
    return r;
}

__device__ __forceinline__ float dd9(float a0, float a1, float a2, float a3, float a4,
                                     float a5, float a6, float a7, float a8) {
    return 0.0625f * (a0 + a8) + 0.25f * (a1 + a7) + 0.25f * (a2 + a6)
         - 0.25f * (a3 + a5) - 0.625f * a4;
}

__global__ void __launch_bounds__(128, 8)
delta_layer_kernel(const float4* __restrict__ x, float4* __restrict__ out) {
    const int d4    = threadIdx.x;                       // 0..63
    const int chunk = blockIdx.x * 2 + threadIdx.y;      // 0..127
    const int b     = blockIdx.y;
    const int t0    = chunk * L_N;

    const float4* __restrict__ xb = x   + (size_t)b * T_N * D4_N  + d4;
    float4*       __restrict__ ob = out + (size_t)b * T_N * OD4_N + d4;

    if (chunk != 0 && chunk != CHUNKS - 1) {
        // ---- interior fast path: 9-deep ring, no clamping needed ----
        float4 r0 = __ldg(xb + (size_t)(t0 - 4) * D4_N);
        float4 r1 = __ldg(xb + (size_t)(t0 - 3) * D4_N);
        float4 r2 = __ldg(xb + (size_t)(t0 - 2) * D4_N);
        float4 r3 = __ldg(xb + (size_t)(t0 - 1) * D4_N);
        float4 r4 = __ldg(xb + (size_t)(t0    ) * D4_N);
        float4 r5 = __ldg(xb + (size_t)(t0 + 1) * D4_N);
        float4 r6 = __ldg(xb + (size_t)(t0 + 2) * D4_N);
        float4 r7 = __ldg(xb + (size_t)(t0 + 3) * D4_N);
        float4 r8 = __ldg(xb + (size_t)(t0 + 4) * D4_N);

#pragma unroll 8
        for (int i = 0; i < L_N; ++i) {
            const int t = t0 + i;
            const size_t orow = (size_t)t * OD4_N;

            __stcs(ob + orow, r4);                              // x
            __stcs(ob + orow + D4_N, f4_delta(r2, r3, r5, r6)); // delta

            float4 dd;
            dd.x = dd9(r0.x, r1.x, r2.x, r3.x, r4.x, r5.x, r6.x, r7.x, r8.x);
            dd.y = dd9(r0.y, r1.y, r2.y, r3.y, r4.y, r5.y, r6.y, r7.y, r8.y);
            dd.z = dd9(r0.z, r1.z, r2.z, r3.z, r4.z, r5.z, r6.z, r7.z, r8.z);
            dd.w = dd9(r0.w, r1.w, r2.w, r3.w, r4.w, r5.w, r6.w, r7.w, r8.w);
            __stcs(ob + orow + 2 * D4_N, dd);                   // double delta

            // shift ring, prefetch x[t+5] (max t0+36 <= T-28 for interior chunks)
            r0 = r1; r1 = r2; r2 = r3; r3 = r4; r4 = r5; r5 = r6; r6 = r7; r7 = r8;
            r8 = __ldg(xb + (size_t)(t + 5) * D4_N);
        }
    } else {
        // ---- edge path: generic clamped math, L1 serves redundant loads ----
        auto LD = [&](int t) -> float4 {
            t = t < 0 ? 0 : (t > T_N - 1 ? T_N - 1 : t);
            return __ldg(xb + (size_t)t * D4_N);
        };
        auto DELTA_AT = [&](int s) -> float4 {
            s = s < 0 ? 0 : (s > T_N - 1 ? T_N - 1 : s);
            return f4_delta(LD(s - 2), LD(s - 1), LD(s + 1), LD(s + 2));
        };

        for (int i = 0; i < L_N; ++i) {
            const int t = t0 + i;
            const size_t orow = (size_t)t * OD4_N;
            ob[orow]        = LD(t);
            ob[orow + D4_N] = DELTA_AT(t);
            ob[orow + 2 * D4_N] =
                f4_delta(DELTA_AT(t - 2), DELTA_AT(t - 1), DELTA_AT(t + 1), DELTA_AT(t + 2));
        }
    }
}

extern "C" void kernel_launch(void* const* d_in, const int* in_sizes, int n_in,
                              void* d_out, int out_size) {
    const float4* x = (const float4*)d_in[0];
    float4* out     = (float4*)d_out;
    // d_in[1] = window (always 2) — baked in.

    dim3 block(D4_N, 2);          // 128 threads, 2 chunks per block
    dim3 grid(CHUNKS / 2, B_N);   // (64, 32) = 2048 blocks
    delta_layer_kernel<<<grid, block>>>(x, out);
}

// round 4
// speedup vs baseline: 1.2361x; 1.0329x over previous
#include <cuda_runtime.h>

// delta_layer: out[b,t,:] = [ x, delta(x), delta(delta(x)) ]
// delta(y)[t] = 0.5*(y[c(t+1)]-y[c(t-1)]) + 0.25*(y[c(t+2)]-y[c(t-2)]), c = clamp [0,T-1]
// Shapes fixed: B=32, T=4096, D=256, window=2.
//
// float2 channel granularity (128 lanes cover D=256) to cut per-thread register
// state (9-deep ring = 18 regs) and reach 12 blocks/SM = 48 warps (75% occ).
// Interior rows use the fused 9-tap double-delta filter:
//   dd(t) = 0.0625(x[t-4]+x[t+4]) + 0.25(x[t-3]+x[t+3]) + 0.25(x[t-2]+x[t+2])
//         - 0.25(x[t-1]+x[t+1]) - 0.625 x[t]

#define B_N 32
#define T_N 4096
#define D2_N 128           // 256 floats / 2
#define OD2_N 384          // 768 floats / 2
#define L_N 32             // rows per thread chunk
#define CHUNKS (T_N / L_N) // 128

__device__ __forceinline__ float2 f2_delta(float2 m2, float2 m1, float2 p1, float2 p2) {
    float2 r;
    r.x = 0.5f * (p1.x - m1.x) + 0.25f * (p2.x - m2.x);
    r.y = 0.5f * (p1.y - m1.y) + 0.25f * (p2.y - m2.y);
    return r;
}

__device__ __forceinline__ float dd9(float a0, float a1, float a2, float a3, float a4,
                                     float a5, float a6, float a7, float a8) {
    return 0.0625f * (a0 + a8) + 0.25f * (a1 + a7) + 0.25f * (a2 + a6)
         - 0.25f * (a3 + a5) - 0.625f * a4;
}

__global__ void __launch_bounds__(128, 12)
delta_layer_kernel(const float2* __restrict__ x, float2* __restrict__ out) {
    const int d2    = threadIdx.x;       // 0..127
    const int chunk = blockIdx.x;        // 0..127
    const int b     = blockIdx.y;
    const int t0    = chunk * L_N;

    const float2* __restrict__ xb = x   + (size_t)b * T_N * D2_N  + d2;
    float2*       __restrict__ ob = out + (size_t)b * T_N * OD2_N + d2;

    if (chunk != 0 && chunk != CHUNKS - 1) {
        // ---- interior fast path: 9-deep float2 ring, no clamping ----
        float2 r0 = __ldg(xb + (size_t)(t0 - 4) * D2_N);
        float2 r1 = __ldg(xb + (size_t)(t0 - 3) * D2_N);
        float2 r2 = __ldg(xb + (size_t)(t0 - 2) * D2_N);
        float2 r3 = __ldg(xb + (size_t)(t0 - 1) * D2_N);
        float2 r4 = __ldg(xb + (size_t)(t0    ) * D2_N);
        float2 r5 = __ldg(xb + (size_t)(t0 + 1) * D2_N);
        float2 r6 = __ldg(xb + (size_t)(t0 + 2) * D2_N);
        float2 r7 = __ldg(xb + (size_t)(t0 + 3) * D2_N);
        float2 r8 = __ldg(xb + (size_t)(t0 + 4) * D2_N);

#pragma unroll 8
        for (int i = 0; i < L_N; ++i) {
            const int t = t0 + i;
            const size_t orow = (size_t)t * OD2_N;

            // prefetch first so the LDG issues ahead of the arithmetic
            float2 nxt = __ldg(xb + (size_t)(t + 5) * D2_N);

            __stcs(ob + orow, r4);                               // x
            __stcs(ob + orow + D2_N, f2_delta(r2, r3, r5, r6));  // delta

            float2 dd;
            dd.x = dd9(r0.x, r1.x, r2.x, r3.x, r4.x, r5.x, r6.x, r7.x, r8.x);
            dd.y = dd9(r0.y, r1.y, r2.y, r3.y, r4.y, r5.y, r6.y, r7.y, r8.y);
            __stcs(ob + orow + 2 * D2_N, dd);                    // double delta

            r0 = r1; r1 = r2; r2 = r3; r3 = r4; r4 = r5; r5 = r6; r6 = r7; r7 = r8;
            r8 = nxt;
        }
    } else {
        // ---- edge path: generic clamped math (2 of 128 chunks) ----
        auto LD = [&](int t) -> float2 {
            t = t < 0 ? 0 : (t > T_N - 1 ? T_N - 1 : t);
            return __ldg(xb + (size_t)t * D2_N);
        };
        auto DELTA_AT = [&](int s) -> float2 {
            s = s < 0 ? 0 : (s > T_N - 1 ? T_N - 1 : s);
            return f2_delta(LD(s - 2), LD(s - 1), LD(s + 1), LD(s + 2));
        };

        for (int i = 0; i < L_N; ++i) {
            const int t = t0 + i;
            const size_t orow = (size_t)t * OD2_N;
            ob[orow]         = LD(t);
            ob[orow + D2_N]  = DELTA_AT(t);
            ob[orow + 2 * D2_N] =
                f2_delta(DELTA_AT(t - 2), DELTA_AT(t - 1), DELTA_AT(t + 1), DELTA_AT(t + 2));
        }
    }
}

extern "C" void kernel_launch(void* const* d_in, const int* in_sizes, int n_in,
                              void* d_out, int out_size) {
    const float2* x = (const float2*)d_in[0];
    float2* out     = (float2*)d_out;
    // d_in[1] = window (always 2) — baked in.

    dim3 block(D2_N, 1);        // 128 threads = 1 chunk
    dim3 grid(CHUNKS, B_N);     // (128, 32) = 4096 blocks
    delta_layer_kernel<<<grid, block>>>(x, out);
}